// round 1
// baseline (speedup 1.0000x reference)
#include <cuda_runtime.h>

// Reference math collapses exactly:
//   p1 has feature dim 1  ->  mu == p1 (exact in fp32)
//   (p1 - mu) == 0 exactly -> var == 0 exactly
//   out = 0/sqrt(eps) * ln_weight + ln_bias = ln_bias
// So out[b] = ln_bias[0] for all b, for ANY x / params / ln_weight.
// We read ln_bias from device memory to stay correct for arbitrary inputs.

__global__ void QuantumGate_65481071410733_kernel(const float* __restrict__ ln_bias,
                                                  float* __restrict__ out,
                                                  int n) {
    int i = blockIdx.x * blockDim.x + threadIdx.x;
    if (i < n) {
        out[i] = ln_bias[0];
    }
}

extern "C" void kernel_launch(void* const* d_in, const int* in_sizes, int n_in,
                              void* d_out, int out_size) {
    // Input order per metadata: x, params, ln_weight, ln_bias
    const float* ln_bias = (const float*)d_in[3];
    float* out = (float*)d_out;
    int n = out_size;  // 512
    int threads = 256;
    int blocks = (n + threads - 1) / threads;
    QuantumGate_65481071410733_kernel<<<blocks, threads>>>(ln_bias, out, n);
}